// round 5
// baseline (speedup 1.0000x reference)
#include <cuda_runtime.h>
#include <math.h>

#define B_    8
#define T_    8
#define C_    256
#define CH_   64
#define Wd    56
#define HW_   3136
#define PT    128
#define NPB   25          // ceil(HW_/PT)

typedef unsigned long long ull;

// ---------------- scratch (device globals) ----------------
__device__ float g_maxavg[(size_t)B_ * T_ * 2 * HW_];
__device__ float g_gate[(size_t)B_ * T_ * HW_];
__device__ __align__(16) ull g_wrd[C_ * 3 * CH_];       // dup'd+swizzled reduce weights
__device__ __align__(16) ull g_wed[CH_ * C_];           // dup'd+swizzled expand weights
__device__ __align__(16) float g_t[(size_t)B_ * CH_ * T_ * HW_];
__device__ __align__(16) float g_xt[(size_t)B_ * C_ * T_ * HW_];
__device__ float g_vpart[(size_t)B_ * C_ * T_ * NPB];
__device__ float g_kern[B_ * C_ * 3];

// ---------------- helpers ----------------
__device__ __forceinline__ void ffma2(ull& d, ull a, ull b) {
    asm("fma.rn.f32x2 %0, %1, %2, %0;" : "+l"(d) : "l"(a), "l"(b));
}
__device__ __forceinline__ ull packdup(float w) {
    ull u; asm("mov.b64 %0, {%1, %1};" : "=l"(u) : "f"(w)); return u;
}
__device__ __forceinline__ float2 unpk(ull u) {
    float2 f; asm("mov.b64 {%0, %1}, %2;" : "=f"(f.x), "=f"(f.y) : "l"(u)); return f;
}
__device__ __forceinline__ unsigned sptr(const void* p) {
    return (unsigned)__cvta_generic_to_shared(p);
}
__device__ __forceinline__ void cpasync16(unsigned dst, const void* src, int bytes) {
    asm volatile("cp.async.ca.shared.global [%0], [%1], 16, %2;"
                 :: "r"(dst), "l"(src), "r"(bytes));
}
__device__ __forceinline__ void cp_commit() { asm volatile("cp.async.commit_group;"); }
__device__ __forceinline__ void cp_wait0()  { asm volatile("cp.async.wait_group 0;"); }

// bank-swizzled position of a channel within an 8x8 group layout
__device__ __forceinline__ int wswiz(int col) {
    int cg = col >> 3, j = (col & 7) >> 1, par = col & 1;
    int jj = (j + (cg >> 1)) & 3;
    return cg * 8 + jj * 2 + par;
}

// ---------------- prep: duplicate+swizzle weights ----------------
__global__ void k_prep(const float* __restrict__ wr, const float* __restrict__ we) {
    int idx = blockIdx.x * blockDim.x + threadIdx.x;
    if (idx < C_ * 3 * CH_) {
        int c = idx / 192;
        int r = idx % 192;
        int dt = r / 64, ch = r % 64;
        g_wrd[c * 192 + dt * 64 + wswiz(ch)] = packdup(wr[ch * (C_ * 3) + c * 3 + dt]);
    }
    if (idx < CH_ * C_) {
        int cin = idx >> 8, co = idx & 255;
        int chunk = co >> 6, col = co & 63;
        g_wed[cin * 256 + chunk * 64 + wswiz(col)] = packdup(we[co * CH_ + cin]);
    }
}

// ---------------- channel max/mean ----------------
__global__ __launch_bounds__(256) void k_maxmean(const float* __restrict__ x) {
    int bt = blockIdx.y;
    int p = blockIdx.x * blockDim.x + threadIdx.x;
    if (p >= HW_) return;
    const float* xp = x + (size_t)bt * C_ * HW_ + p;
    float mx = -INFINITY, sm = 0.f;
#pragma unroll 4
    for (int c = 0; c < C_; c++) {
        float v = xp[(size_t)c * HW_];
        mx = fmaxf(mx, v);
        sm += v;
    }
    g_maxavg[(size_t)bt * 2 * HW_ + p] = mx;
    g_maxavg[(size_t)bt * 2 * HW_ + HW_ + p] = sm * (1.f / C_);
}

// ---------------- 7x7 conv -> spatial gate ----------------
__global__ __launch_bounds__(256) void k_spatial(const float* __restrict__ w) {
    __shared__ float sw[98];
    int tid = threadIdx.x;
    if (tid < 98) sw[tid] = w[tid];
    __syncthreads();
    int bt = blockIdx.y;
    int p = blockIdx.x * blockDim.x + tid;
    if (p >= HW_) return;
    int py = p / Wd, px = p % Wd;
    const float* mb = g_maxavg + (size_t)bt * 2 * HW_;
    float s = 0.f;
#pragma unroll
    for (int ky = 0; ky < 7; ky++) {
        int iy = py + ky - 3;
        if (iy < 0 || iy >= Wd) continue;
#pragma unroll
        for (int kx = 0; kx < 7; kx++) {
            int ix = px + kx - 3;
            if (ix < 0 || ix >= Wd) continue;
            float m = mb[iy * Wd + ix];
            float a = mb[HW_ + iy * Wd + ix];
            s += sw[ky * 7 + kx] * m + sw[49 + ky * 7 + kx] * a;
        }
    }
    g_gate[(size_t)bt * HW_ + p] = 1.f + 1.f / (1.f + __expf(-s));
}

// ---------------- fused gated reduce conv3d GEMM (64 x 128, K=768) + BN + relu ----------------
// 128 thr = 4 warps, each warp 32 px. Lane = 8(chg) x 4(pxg); lane tile 8ch x 8px.
__global__ __launch_bounds__(128, 3) void k_reduce(
    const float* __restrict__ x, const float* __restrict__ gamma,
    const float* __restrict__ beta, const float* __restrict__ mean,
    const float* __restrict__ var) {
    __shared__ __align__(16) float sgate[3][PT];        // 1.5KB
    __shared__ __align__(16) float sxs[8][3][PT];       // 12KB
    __shared__ __align__(16) ull swd[2][1536];          // 24KB double-buffered

    int tid = threadIdx.x;
    int p0 = blockIdx.x * PT;
    int t = blockIdx.y, b = blockIdx.z;

    for (int i = tid; i < 3 * PT; i += 128) {
        int dt = i / PT, p = i % PT;
        int tin = t + dt - 1;
        float g = 0.f;
        if (tin >= 0 && tin < T_ && p0 + p < HW_)
            g = g_gate[(size_t)(b * T_ + tin) * HW_ + p0 + p];
        sgate[dt][p] = g;
    }

    int warp = tid >> 5, lane = tid & 31;
    int chg = lane & 7, pxg = lane >> 3;
    int pxb = warp * 32 + pxg * 8;
    int rot = (chg >> 1) & 3;

    ull acc[8][4];
#pragma unroll
    for (int i = 0; i < 8; i++)
#pragma unroll
        for (int j = 0; j < 4; j++) acc[i][j] = 0ULL;

    const float* xb = x + (size_t)b * T_ * C_ * HW_;

    // per-thread x staging slots (6 float4 per chunk)
    float4 xf[6];
    int xcc[6], xdt[6], xp4[6], xok[6];
#pragma unroll
    for (int k = 0; k < 6; k++) {
        int i = tid + k * 128;            // < 768
        xcc[k] = i / 96;
        int r = i % 96;
        xdt[k] = r / 32;
        xp4[k] = (r & 31) << 2;
        int tin = t + xdt[k] - 1;
        xok[k] = (tin >= 0 && tin < T_ && p0 + xp4[k] < HW_) ? tin : -1;
    }

    unsigned swd_s = sptr(&swd[0][0]);

    // prologue: weights chunk0 via cp.async, x chunk0 via LDG
#pragma unroll
    for (int k = 0; k < 6; k++) {
        int q = tid + k * 128;
        cpasync16(swd_s + q * 16, g_wrd + q * 2, 16);
    }
    cp_commit();
#pragma unroll
    for (int k = 0; k < 6; k++) {
        xf[k] = make_float4(0.f, 0.f, 0.f, 0.f);
        if (xok[k] >= 0)
            xf[k] = *(const float4*)(xb + ((size_t)(xok[k] * C_ + xcc[k])) * HW_ + p0 + xp4[k]);
    }

    for (int c0 = 0; c0 < C_; c0 += 8) {
        int buf = (c0 >> 3) & 1;
        __syncthreads();                 // sxs free from previous compute
#pragma unroll
        for (int k = 0; k < 6; k++) {
            float4 v = xf[k];
            float4 g = *(const float4*)&sgate[xdt[k]][xp4[k]];
            v.x *= g.x; v.y *= g.y; v.z *= g.z; v.w *= g.w;
            *(float4*)&sxs[xcc[k]][xdt[k]][xp4[k]] = v;
        }
        cp_wait0();
        __syncthreads();                 // sxs + swd[buf] visible

        if (c0 + 8 < C_) {
#pragma unroll
            for (int k = 0; k < 6; k++) {
                int q = tid + k * 128;
                cpasync16(swd_s + (buf ^ 1) * 12288 + q * 16,
                          g_wrd + (c0 + 8) * 192 + q * 2, 16);
            }
            cp_commit();
#pragma unroll
            for (int k = 0; k < 6; k++) {
                xf[k] = make_float4(0.f, 0.f, 0.f, 0.f);
                if (xok[k] >= 0)
                    xf[k] = *(const float4*)(xb + ((size_t)(xok[k] * C_ + c0 + 8 + xcc[k])) * HW_ + p0 + xp4[k]);
            }
        }

#pragma unroll 4
        for (int cc = 0; cc < 8; cc++) {
#pragma unroll
            for (int dt = 0; dt < 3; dt++) {
                const ull* wrow = &swd[buf][cc * 192 + dt * 64 + chg * 8];
                ull wd[8];
#pragma unroll
                for (int j = 0; j < 4; j++) {
                    int jj = (j + rot) & 3;
                    ulonglong2 wp = *(const ulonglong2*)&wrow[jj * 2];
                    wd[2 * j] = wp.x;
                    wd[2 * j + 1] = wp.y;
                }
                ulonglong2 xa = *(const ulonglong2*)(const void*)&sxs[cc][dt][pxb];
                ulonglong2 xc = *(const ulonglong2*)(const void*)&sxs[cc][dt][pxb + 4];
                ull xv[4] = {xa.x, xa.y, xc.x, xc.y};
#pragma unroll
                for (int i = 0; i < 8; i++)
#pragma unroll
                    for (int j = 0; j < 4; j++)
                        ffma2(acc[i][j], wd[i], xv[j]);
            }
        }
    }

    // BN + relu epilogue: lane writes 8ch x 8px
    if (p0 + pxb < HW_) {
#pragma unroll
        for (int i = 0; i < 8; i++) {
            int ch = chg * 8 + i;
            float inv = gamma[ch] * rsqrtf(var[ch] + 1e-5f);
            float bia = beta[ch] - mean[ch] * inv;
            float* dst = g_t + ((size_t)((b * CH_ + ch) * T_ + t)) * HW_ + p0 + pxb;
            float2 f0 = unpk(acc[i][0]), f1 = unpk(acc[i][1]);
            float2 f2 = unpk(acc[i][2]), f3 = unpk(acc[i][3]);
            float4 oA, oB;
            oA.x = fmaxf(fmaf(f0.x, inv, bia), 0.f);
            oA.y = fmaxf(fmaf(f0.y, inv, bia), 0.f);
            oA.z = fmaxf(fmaf(f1.x, inv, bia), 0.f);
            oA.w = fmaxf(fmaf(f1.y, inv, bia), 0.f);
            oB.x = fmaxf(fmaf(f2.x, inv, bia), 0.f);
            oB.y = fmaxf(fmaf(f2.y, inv, bia), 0.f);
            oB.z = fmaxf(fmaf(f3.x, inv, bia), 0.f);
            oB.w = fmaxf(fmaf(f3.y, inv, bia), 0.f);
            *(float4*)dst = oA;
            *(float4*)(dst + 4) = oB;
        }
    }
}

// ---------------- expand 1x1x1 GEMM (256 x 128, K=64) + sigmoid + x_t + v partials ----------------
// 128 thr; 4 co-chunks of 64; lane tile 8co x 8px. Dynamic smem: st 32KB + w 2x32KB + sred.
__global__ __launch_bounds__(128, 2) void k_expand(const float* __restrict__ x) {
    extern __shared__ __align__(16) char dynbuf[];
    float (*st)[PT] = (float(*)[PT])dynbuf;                       // 64x128 f32 = 32KB
    ull* swd = (ull*)(dynbuf + CH_ * PT * 4);                     // 2x4096 ull = 64KB
    float (*sred)[64] = (float(*)[64])(dynbuf + CH_ * PT * 4 + 2 * 4096 * 8); // 4x64 f32

    int tid = threadIdx.x;
    int p0 = blockIdx.x * PT;
    int t = blockIdx.y, b = blockIdx.z;
    int warp = tid >> 5, lane = tid & 31;
    int cog = lane & 7, pxg = lane >> 3;
    int pxb = warp * 32 + pxg * 8;
    int rot = (cog >> 1) & 3;
    bool pv = (p0 + pxb < HW_);

    unsigned st_s = sptr(&st[0][0]);
    unsigned swd_s = sptr(swd);

    // prologue: stage t-tile + weight chunk0
    const float* tsrc = g_t + ((size_t)(b * CH_ * T_ + t)) * HW_;
#pragma unroll
    for (int k = 0; k < 16; k++) {
        int q = tid + k * 128;            // < 2048 (16B units)
        int cin = q >> 5, c16 = q & 31;
        int bytes = (p0 + c16 * 4 < HW_) ? 16 : 0;
        cpasync16(st_s + q * 16, tsrc + (size_t)cin * T_ * HW_ + p0 + c16 * 4, bytes);
    }
#pragma unroll
    for (int k = 0; k < 16; k++) {
        int q = tid + k * 128;            // < 2048
        int cin = q >> 5, off = (q & 31) * 2;
        cpasync16(swd_s + q * 16, g_wed + cin * 256 + off, 16);
    }
    cp_commit();

    float4 gvA = make_float4(0.f, 0.f, 0.f, 0.f), gvB = gvA;
    if (pv) {
        const float* gp = g_gate + (size_t)(b * T_ + t) * HW_ + p0 + pxb;
        gvA = *(const float4*)gp;
        gvB = *(const float4*)(gp + 4);
    }

    for (int chunk = 0; chunk < 4; chunk++) {
        int buf = chunk & 1;
        cp_wait0();
        __syncthreads();

        if (chunk < 3) {
#pragma unroll
            for (int k = 0; k < 16; k++) {
                int q = tid + k * 128;
                int cin = q >> 5, off = (q & 31) * 2;
                cpasync16(swd_s + (buf ^ 1) * 32768 + q * 16,
                          g_wed + cin * 256 + (chunk + 1) * 64 + off, 16);
            }
            cp_commit();
        }

        ull acc[8][4];
#pragma unroll
        for (int i = 0; i < 8; i++)
#pragma unroll
            for (int j = 0; j < 4; j++) acc[i][j] = 0ULL;

#pragma unroll 8
        for (int cin = 0; cin < CH_; cin++) {
            const ull* wrow = &swd[buf * 4096 + cin * 64 + cog * 8];
            ull wd[8];
#pragma unroll
            for (int j = 0; j < 4; j++) {
                int jj = (j + rot) & 3;
                ulonglong2 wp = *(const ulonglong2*)&wrow[jj * 2];
                wd[2 * j] = wp.x;
                wd[2 * j + 1] = wp.y;
            }
            ulonglong2 xa = *(const ulonglong2*)(const void*)&st[cin][pxb];
            ulonglong2 xc = *(const ulonglong2*)(const void*)&st[cin][pxb + 4];
            ull xv[4] = {xa.x, xa.y, xc.x, xc.y};
#pragma unroll
            for (int i = 0; i < 8; i++)
#pragma unroll
                for (int j = 0; j < 4; j++)
                    ffma2(acc[i][j], wd[i], xv[j]);
        }

        // epilogue: x_t = x*gate*(1+sigmoid)  [1+sig(s) = 2 - 1/(1+e^s)]
        float psum[8];
#pragma unroll
        for (int i = 0; i < 8; i++) {
            psum[i] = 0.f;
            if (pv) {
                int co = chunk * 64 + cog * 8 + i;
                const float* xsrc = x + ((size_t)((b * T_ + t) * C_ + co)) * HW_ + p0 + pxb;
                float* dst = g_xt + ((size_t)((b * C_ + co) * T_ + t)) * HW_ + p0 + pxb;
                float4 xA = *(const float4*)xsrc, xB = *(const float4*)(xsrc + 4);
                float2 f0 = unpk(acc[i][0]), f1 = unpk(acc[i][1]);
                float2 f2 = unpk(acc[i][2]), f3 = unpk(acc[i][3]);
                float4 oA, oB;
                oA.x = xA.x * gvA.x * (2.f - 1.f / (1.f + __expf(f0.x)));
                oA.y = xA.y * gvA.y * (2.f - 1.f / (1.f + __expf(f0.y)));
                oA.z = xA.z * gvA.z * (2.f - 1.f / (1.f + __expf(f1.x)));
                oA.w = xA.w * gvA.w * (2.f - 1.f / (1.f + __expf(f1.y)));
                oB.x = xB.x * gvB.x * (2.f - 1.f / (1.f + __expf(f2.x)));
                oB.y = xB.y * gvB.y * (2.f - 1.f / (1.f + __expf(f2.y)));
                oB.z = xB.z * gvB.z * (2.f - 1.f / (1.f + __expf(f3.x)));
                oB.w = xB.w * gvB.w * (2.f - 1.f / (1.f + __expf(f3.y)));
                *(float4*)dst = oA;
                *(float4*)(dst + 4) = oB;
                psum[i] = (oA.x + oA.y) + (oA.z + oA.w) + (oB.x + oB.y) + (oB.z + oB.w);
            }
        }
#pragma unroll
        for (int i = 0; i < 8; i++) {
            psum[i] += __shfl_xor_sync(0xffffffffu, psum[i], 8);
            psum[i] += __shfl_xor_sync(0xffffffffu, psum[i], 16);
        }
        if (pxg == 0) {
#pragma unroll
            for (int i = 0; i < 8; i++) sred[warp][cog * 8 + i] = psum[i];
        }
        __syncthreads();
        if (tid < 64) {
            float s = sred[0][tid] + sred[1][tid] + sred[2][tid] + sred[3][tid];
            g_vpart[((size_t)((b * C_ + chunk * 64 + tid) * T_ + t)) * NPB + blockIdx.x] = s;
        }
    }
}

// ---------------- dynamic temporal kernel ----------------
__global__ __launch_bounds__(256) void k_dyn(
    const float* __restrict__ wfc1, const float* __restrict__ bfc1,
    const float* __restrict__ wfc2, const float* __restrict__ bfc2) {
    int id = blockIdx.x * blockDim.x + threadIdx.x;
    if (id >= B_ * C_) return;
    float v[T_];
#pragma unroll
    for (int t = 0; t < T_; t++) {
        const float* pp = g_vpart + ((size_t)id * T_ + t) * NPB;
        float s = 0.f;
#pragma unroll
        for (int k = 0; k < NPB; k++) s += pp[k];
        v[t] = s * (1.f / HW_);
    }
    float lg[3] = {bfc2[0], bfc2[1], bfc2[2]};
#pragma unroll
    for (int hh = 0; hh < 16; hh++) {
        float s = bfc1[hh];
#pragma unroll
        for (int t = 0; t < T_; t++) s += wfc1[hh * 8 + t] * v[t];
        s = fmaxf(s, 0.f);
#pragma unroll
        for (int k = 0; k < 3; k++) lg[k] += wfc2[k * 16 + hh] * s;
    }
    float m = fmaxf(lg[0], fmaxf(lg[1], lg[2]));
    float e0 = __expf(lg[0] - m), e1 = __expf(lg[1] - m), e2 = __expf(lg[2] - m);
    float inv = 1.f / (e0 + e1 + e2);
    g_kern[id * 3 + 0] = e0 * inv;
    g_kern[id * 3 + 1] = e1 * inv;
    g_kern[id * 3 + 2] = e2 * inv;
}

// ---------------- depthwise temporal stencil ----------------
__global__ __launch_bounds__(256) void k_stencil(float* __restrict__ out) {
    int p = blockIdx.x * blockDim.x + threadIdx.x;
    if (p >= HW_) return;
    int bc = blockIdx.y;
    int b = bc >> 8, c = bc & 255;
    float k0 = g_kern[bc * 3 + 0];
    float k1 = g_kern[bc * 3 + 1];
    float k2 = g_kern[bc * 3 + 2];
    const float* src = g_xt + (size_t)bc * T_ * HW_ + p;
    float prev = 0.f, cur = src[0];
#pragma unroll
    for (int t = 0; t < T_; t++) {
        float nxt = (t < T_ - 1) ? src[(size_t)(t + 1) * HW_] : 0.f;
        out[((size_t)((b * T_ + t) * C_ + c)) * HW_ + p] = k0 * prev + k1 * cur + k2 * nxt;
        prev = cur;
        cur = nxt;
    }
}

// ---------------- launch ----------------
extern "C" void kernel_launch(void* const* d_in, const int* in_sizes, int n_in,
                              void* d_out, int out_size) {
    const float* x      = (const float*)d_in[0];
    const float* w_sp   = (const float*)d_in[1];
    const float* w_red  = (const float*)d_in[2];
    const float* gam    = (const float*)d_in[3];
    const float* bet    = (const float*)d_in[4];
    const float* mea    = (const float*)d_in[5];
    const float* var    = (const float*)d_in[6];
    const float* w_exp  = (const float*)d_in[7];
    const float* wfc1   = (const float*)d_in[8];
    const float* bfc1   = (const float*)d_in[9];
    const float* wfc2   = (const float*)d_in[10];
    const float* bfc2   = (const float*)d_in[11];
    float* out = (float*)d_out;

    const int EXP_SMEM = CH_ * PT * 4 + 2 * 4096 * 8 + 4 * 64 * 4;  // 99328B
    cudaFuncSetAttribute(k_expand, cudaFuncAttributeMaxDynamicSharedMemorySize, EXP_SMEM);

    k_prep<<<192, 256>>>(w_red, w_exp);   // FIX: must cover C_*3*CH_ = 49152 g_wrd entries
    k_maxmean<<<dim3(13, B_ * T_), 256>>>(x);
    k_spatial<<<dim3(13, B_ * T_), 256>>>(w_sp);
    k_reduce<<<dim3(NPB, T_, B_), 128>>>(x, gam, bet, mea, var);
    k_expand<<<dim3(NPB, T_, B_), 128, EXP_SMEM>>>(x);
    k_dyn<<<8, 256>>>(wfc1, bfc1, wfc2, bfc2);
    k_stencil<<<dim3(13, B_ * C_), 256>>>(out);
}

// round 7
// speedup vs baseline: 1.2236x; 1.2236x over previous
#include <cuda_runtime.h>
#include <math.h>
#include <stdint.h>

#define B_    8
#define T_    8
#define C_    256
#define CH_   64
#define Wd    56
#define HW_   3136
#define PT    128
#define NPB   25          // ceil(HW_/PT) for expand
#define PXT   16          // px per block in k_reduce (HW_/PXT = 196 exact)

typedef unsigned long long ull;

// ---------------- scratch (device globals) ----------------
__device__ float g_maxavg[(size_t)B_ * T_ * 2 * HW_];
__device__ float g_gate[(size_t)B_ * T_ * HW_];
__device__ __align__(16) float g_wrf[C_ * 3 * CH_];     // [c*192 + dt*64 + ch] plain f32
__device__ float g_we[CH_ * C_];                        // [cin*256 + cout]
__device__ __align__(16) float g_t[(size_t)B_ * CH_ * T_ * HW_];
__device__ __align__(16) float g_xt[(size_t)B_ * C_ * T_ * HW_];
__device__ float g_vpart[(size_t)B_ * C_ * T_ * NPB];
__device__ float g_kern[B_ * C_ * 3];

// ---------------- helpers ----------------
__device__ __forceinline__ void ffma2(ull& d, ull a, ull b) {
    asm("fma.rn.f32x2 %0, %1, %2, %0;" : "+l"(d) : "l"(a), "l"(b));
}
__device__ __forceinline__ ull packdup(float w) {
    ull u; asm("mov.b64 %0, {%1, %1};" : "=l"(u) : "f"(w)); return u;
}
__device__ __forceinline__ float2 unpk(ull u) {
    float2 f; asm("mov.b64 {%0, %1}, %2;" : "=f"(f.x), "=f"(f.y) : "l"(u)); return f;
}
__device__ __forceinline__ unsigned sptr(const void* p) {
    return (unsigned)__cvta_generic_to_shared(p);
}
__device__ __forceinline__ void cpasync16(unsigned dst, const void* src) {
    asm volatile("cp.async.ca.shared.global [%0], [%1], 16;" :: "r"(dst), "l"(src));
}
__device__ __forceinline__ void cp_commit() { asm volatile("cp.async.commit_group;"); }
__device__ __forceinline__ void cp_wait0()  { asm volatile("cp.async.wait_group 0;"); }

// ---------------- prep: weight transposes ----------------
__global__ void k_prep(const float* __restrict__ wr, const float* __restrict__ we) {
    int idx = blockIdx.x * blockDim.x + threadIdx.x;
    if (idx < C_ * 3 * CH_) {
        int c = idx / 192;
        int r = idx % 192;
        int dt = r / 64, ch = r % 64;
        g_wrf[idx] = wr[ch * (C_ * 3) + c * 3 + dt];
    }
    if (idx < CH_ * C_) {
        int cout = idx & 255, cin = idx >> 8;
        g_we[idx] = we[cout * CH_ + cin];
    }
}

// ---------------- channel max/mean ----------------
__global__ __launch_bounds__(256) void k_maxmean(const float* __restrict__ x) {
    int bt = blockIdx.y;
    int p = blockIdx.x * blockDim.x + threadIdx.x;
    if (p >= HW_) return;
    const float* xp = x + (size_t)bt * C_ * HW_ + p;
    float mx = -INFINITY, sm = 0.f;
#pragma unroll 4
    for (int c = 0; c < C_; c++) {
        float v = xp[(size_t)c * HW_];
        mx = fmaxf(mx, v);
        sm += v;
    }
    g_maxavg[(size_t)bt * 2 * HW_ + p] = mx;
    g_maxavg[(size_t)bt * 2 * HW_ + HW_ + p] = sm * (1.f / C_);
}

// ---------------- 7x7 conv -> spatial gate ----------------
__global__ __launch_bounds__(256) void k_spatial(const float* __restrict__ w) {
    __shared__ float sw[98];
    int tid = threadIdx.x;
    if (tid < 98) sw[tid] = w[tid];
    __syncthreads();
    int bt = blockIdx.y;
    int p = blockIdx.x * blockDim.x + tid;
    if (p >= HW_) return;
    int py = p / Wd, px = p % Wd;
    const float* mb = g_maxavg + (size_t)bt * 2 * HW_;
    float s = 0.f;
#pragma unroll
    for (int ky = 0; ky < 7; ky++) {
        int iy = py + ky - 3;
        if (iy < 0 || iy >= Wd) continue;
#pragma unroll
        for (int kx = 0; kx < 7; kx++) {
            int ix = px + kx - 3;
            if (ix < 0 || ix >= Wd) continue;
            float m = mb[iy * Wd + ix];
            float a = mb[HW_ + iy * Wd + ix];
            s += sw[ky * 7 + kx] * m + sw[49 + ky * 7 + kx] * a;
        }
    }
    g_gate[(size_t)bt * HW_ + p] = 1.f + 1.f / (1.f + __expf(-s));
}

// ---------------- t-batched gated reduce conv3d + BN + relu ----------------
// Block: (px-tile of 16, b). ALL 8 output t's per block.
// 128 thr = 4 warps; lane = 16(chg) x 2(pxg); lane tile 4ch x 8t x 2px.
// Per k-element c: xs window (10 t-slots, pair) reused by 3dt x 4ch FFMA2.
__global__ __launch_bounds__(128) void k_reduce(
    const float* __restrict__ x, const float* __restrict__ gamma,
    const float* __restrict__ beta, const float* __restrict__ mean,
    const float* __restrict__ var) {
    __shared__ float sinv[64], sbias[64];
    __shared__ __align__(16) ull sg[8][8];          // gate pairs [tin][pair]
    __shared__ __align__(16) ull sxs[8][8][10];     // [c][pair][slot] slot=tin+1, 5KB
    __shared__ __align__(16) float swf[2][1536];    // weights f32, 12KB dbl-buffered

    int tid = threadIdx.x;
    int warp = tid >> 5, lane = tid & 31;
    int chg = lane & 15, pxg = lane >> 4;
    int pair = warp * 2 + pxg;                      // 0..7
    int p0 = blockIdx.x * PXT;
    int b = blockIdx.y;

    if (tid < 64) {
        float iv = gamma[tid] * rsqrtf(var[tid] + 1e-5f);
        sinv[tid] = iv;
        sbias[tid] = beta[tid] - mean[tid] * iv;
    }
    // gate staging: thread<64 -> (tin = k>>3, pair = k&7)
    if (tid < 64) {
        int tin = tid >> 3, pr = tid & 7;
        float2 g = *(const float2*)(g_gate + (size_t)(b * T_ + tin) * HW_ + p0 + pr * 2);
        sg[tin][pr] = *(ull*)&g;
    }
    // zero pads (slots 0 and 9), persist across chunks
    if (tid < 64) {
        int c = tid >> 3, pr = tid & 7;
        sxs[c][pr][0] = 0ULL;
        sxs[c][pr][9] = 0ULL;
    }
    __syncthreads();

    // staging decode: thread -> (c = tid>>4, pair = tid&7, half = (tid>>3)&1 -> tins half*4..+3)
    int sc = tid >> 4, sp = tid & 7, shalf = (tid >> 3) & 1;
    const float* xb = x + ((size_t)b * T_ * C_) * HW_ + p0 + sp * 2;
    float2 sgate[4];
#pragma unroll
    for (int k = 0; k < 4; k++) {
        ull g = sg[shalf * 4 + k][sp];
        sgate[k] = unpk(g);
    }

    unsigned swf_s = sptr(&swf[0][0]);

    // prologue: w chunk0 via cp.async (8c x 192 f32 = 6KB = 384 x 16B, 3/thread)
#pragma unroll
    for (int k = 0; k < 3; k++) {
        int q = tid + k * 128;
        cpasync16(swf_s + q * 16, g_wrf + q * 4);
    }
    cp_commit();
    // x chunk0 prefetch: 4 float2
    float2 xf[4];
#pragma unroll
    for (int k = 0; k < 4; k++) {
        int tin = shalf * 4 + k;
        xf[k] = *(const float2*)(xb + ((size_t)(tin * C_ + sc)) * HW_);
    }

    ull acc[4][8];
#pragma unroll
    for (int i = 0; i < 4; i++)
#pragma unroll
        for (int t = 0; t < 8; t++) acc[i][t] = 0ULL;

    for (int c0 = 0; c0 < C_; c0 += 8) {
        int buf = (c0 >> 3) & 1;
        __syncthreads();                 // xs free from previous compute
        // store staged x * gate to slots 1..8
#pragma unroll
        for (int k = 0; k < 4; k++) {
            float2 v;
            v.x = xf[k].x * sgate[k].x;
            v.y = xf[k].y * sgate[k].y;
            sxs[sc][sp][1 + shalf * 4 + k] = *(ull*)&v;
        }
        cp_wait0();
        __syncthreads();                 // xs + swf[buf] visible

        if (c0 + 8 < C_) {
#pragma unroll
            for (int k = 0; k < 3; k++) {
                int q = tid + k * 128;
                cpasync16(swf_s + (buf ^ 1) * 6144 + q * 16,
                          g_wrf + (c0 + 8) * 192 + q * 4);
            }
            cp_commit();
#pragma unroll
            for (int k = 0; k < 4; k++) {
                int tin = shalf * 4 + k;
                xf[k] = *(const float2*)(xb + ((size_t)(tin * C_ + c0 + 8 + sc)) * HW_);
            }
        }

#pragma unroll 2
        for (int cc = 0; cc < 8; cc++) {
            // x window: 10 ull via 5 LDS.128
            const ulonglong2* xp2 = (const ulonglong2*)&sxs[cc][pair][0];
            ulonglong2 a0 = xp2[0], a1 = xp2[1], a2 = xp2[2], a3 = xp2[3], a4 = xp2[4];
            ull xv[10] = {a0.x, a0.y, a1.x, a1.y, a2.x, a2.y, a3.x, a3.y, a4.x, a4.y};
#pragma unroll
            for (int dt = 0; dt < 3; dt++) {
                float4 wq = *(const float4*)&swf[buf][cc * 192 + dt * 64 + chg * 4];
                ull w0 = packdup(wq.x), w1 = packdup(wq.y);
                ull w2 = packdup(wq.z), w3 = packdup(wq.w);
#pragma unroll
                for (int t = 0; t < 8; t++) {
                    ffma2(acc[0][t], w0, xv[t + dt]);
                    ffma2(acc[1][t], w1, xv[t + dt]);
                    ffma2(acc[2][t], w2, xv[t + dt]);
                    ffma2(acc[3][t], w3, xv[t + dt]);
                }
            }
        }
    }

    // epilogue: BN + relu, lane writes 4ch x 8t x 2px
    int px = p0 + pair * 2;
#pragma unroll
    for (int i = 0; i < 4; i++) {
        int ch = chg * 4 + i;
        float inv = sinv[ch], bia = sbias[ch];
        float* dst = g_t + (((size_t)(b * CH_ + ch)) * T_) * HW_ + px;
#pragma unroll
        for (int t = 0; t < 8; t++) {
            float2 f = unpk(acc[i][t]);
            float2 o;
            o.x = fmaxf(fmaf(f.x, inv, bia), 0.f);
            o.y = fmaxf(fmaf(f.y, inv, bia), 0.f);
            *(float2*)(dst + (size_t)t * HW_) = o;
        }
    }
}

// ---------------- expand 1x1x1 GEMM (256 x 128, K=64) + sigmoid + x_t + v partials ----------------
__global__ __launch_bounds__(256, 2) void k_expand(const float* __restrict__ x) {
    __shared__ __align__(16) float st[CH_][PT];         // 32KB
    __shared__ __align__(16) float swi2[CH_ * 64];      // 16KB interleaved
    __shared__ float sred[8][64];                       // 2KB

    int tid = threadIdx.x;
    int p0 = blockIdx.x * PT;
    int t = blockIdx.y, b = blockIdx.z;
    int warp = tid >> 5, lane = tid & 31;
    int cog = lane & 7, pxg = lane >> 3;
    int pxb = warp * 16 + pxg * 4;
    bool pv = (p0 + pxb < HW_);

    const float* tsrc = g_t + ((size_t)(b * CH_ * T_ + t)) * HW_;
#pragma unroll
    for (int k = 0; k < 8; k++) {
        int i = tid + k * 256;
        int cin = i >> 5, p4 = (i & 31) << 2;
        float4 v = make_float4(0.f, 0.f, 0.f, 0.f);
        if (p0 + p4 < HW_)
            v = *(const float4*)(tsrc + (size_t)cin * T_ * HW_ + p0 + p4);
        *(float4*)&st[cin][p4] = v;
    }

    float4 gv = make_float4(0.f, 0.f, 0.f, 0.f);
    if (pv) gv = *(const float4*)(g_gate + (size_t)(b * T_ + t) * HW_ + p0 + pxb);

    for (int chunk = 0; chunk < 4; chunk++) {
        int co0 = chunk * 64;
        __syncthreads();
#pragma unroll
        for (int k = 0; k < 16; k++) {
            int o = tid + k * 256;
            int cin = o >> 6, q = o & 63;
            int half = q >> 5, cg = (q >> 2) & 7, ii = q & 3;
            swi2[o] = g_we[cin * C_ + co0 + cg * 8 + half * 4 + ii];
        }
        __syncthreads();

        ull acc[8][2];
#pragma unroll
        for (int i = 0; i < 8; i++) { acc[i][0] = 0ULL; acc[i][1] = 0ULL; }

#pragma unroll 8
        for (int cin = 0; cin < CH_; cin++) {
            const float* wrow = &swi2[cin * 64];
            float4 wlo = *(const float4*)(wrow + cog * 4);
            float4 whi = *(const float4*)(wrow + 32 + cog * 4);
            ull wd[8];
            wd[0] = packdup(wlo.x); wd[1] = packdup(wlo.y);
            wd[2] = packdup(wlo.z); wd[3] = packdup(wlo.w);
            wd[4] = packdup(whi.x); wd[5] = packdup(whi.y);
            wd[6] = packdup(whi.z); wd[7] = packdup(whi.w);
            ulonglong2 xv = *(const ulonglong2*)(const void*)&st[cin][pxb];
#pragma unroll
            for (int j = 0; j < 8; j++) {
                ffma2(acc[j][0], wd[j], xv.x);
                ffma2(acc[j][1], wd[j], xv.y);
            }
        }

        float psum[8];
#pragma unroll
        for (int j = 0; j < 8; j++) {
            psum[j] = 0.f;
            if (pv) {
                int co = co0 + cog * 8 + j;
                float4 xin = *(const float4*)(x + ((size_t)((b * T_ + t) * C_ + co)) * HW_ + p0 + pxb);
                float2 f0 = unpk(acc[j][0]);
                float2 f1 = unpk(acc[j][1]);
                float4 o;
                o.x = xin.x * gv.x * (2.f - 1.f / (1.f + __expf(f0.x)));
                o.y = xin.y * gv.y * (2.f - 1.f / (1.f + __expf(f0.y)));
                o.z = xin.z * gv.z * (2.f - 1.f / (1.f + __expf(f1.x)));
                o.w = xin.w * gv.w * (2.f - 1.f / (1.f + __expf(f1.y)));
                *(float4*)(g_xt + ((size_t)((b * C_ + co) * T_ + t)) * HW_ + p0 + pxb) = o;
                psum[j] = o.x + o.y + o.z + o.w;
            }
        }
#pragma unroll
        for (int j = 0; j < 8; j++) {
            psum[j] += __shfl_xor_sync(0xffffffffu, psum[j], 8);
            psum[j] += __shfl_xor_sync(0xffffffffu, psum[j], 16);
        }
        if (pxg == 0) {
#pragma unroll
            for (int j = 0; j < 8; j++)
                sred[warp][cog * 8 + j] = psum[j];
        }
        __syncthreads();
        if (tid < 64) {
            float s = 0.f;
#pragma unroll
            for (int w = 0; w < 8; w++) s += sred[w][tid];
            g_vpart[((size_t)((b * C_ + co0 + tid) * T_ + t)) * NPB + blockIdx.x] = s;
        }
    }
}

// ---------------- dynamic temporal kernel ----------------
__global__ __launch_bounds__(256) void k_dyn(
    const float* __restrict__ wfc1, const float* __restrict__ bfc1,
    const float* __restrict__ wfc2, const float* __restrict__ bfc2) {
    int id = blockIdx.x * blockDim.x + threadIdx.x;
    if (id >= B_ * C_) return;
    float v[T_];
#pragma unroll
    for (int t = 0; t < T_; t++) {
        const float* pp = g_vpart + ((size_t)id * T_ + t) * NPB;
        float s = 0.f;
#pragma unroll
        for (int k = 0; k < NPB; k++) s += pp[k];
        v[t] = s * (1.f / HW_);
    }
    float lg[3] = {bfc2[0], bfc2[1], bfc2[2]};
#pragma unroll
    for (int hh = 0; hh < 16; hh++) {
        float s = bfc1[hh];
#pragma unroll
        for (int t = 0; t < T_; t++) s += wfc1[hh * 8 + t] * v[t];
        s = fmaxf(s, 0.f);
#pragma unroll
        for (int k = 0; k < 3; k++) lg[k] += wfc2[k * 16 + hh] * s;
    }
    float m = fmaxf(lg[0], fmaxf(lg[1], lg[2]));
    float e0 = __expf(lg[0] - m), e1 = __expf(lg[1] - m), e2 = __expf(lg[2] - m);
    float inv = 1.f / (e0 + e1 + e2);
    g_kern[id * 3 + 0] = e0 * inv;
    g_kern[id * 3 + 1] = e1 * inv;
    g_kern[id * 3 + 2] = e2 * inv;
}

// ---------------- depthwise temporal stencil ----------------
__global__ __launch_bounds__(256) void k_stencil(float* __restrict__ out) {
    int p = blockIdx.x * blockDim.x + threadIdx.x;
    if (p >= HW_) return;
    int bc = blockIdx.y;
    int b = bc >> 8, c = bc & 255;
    float k0 = g_kern[bc * 3 + 0];
    float k1 = g_kern[bc * 3 + 1];
    float k2 = g_kern[bc * 3 + 2];
    const float* src = g_xt + (size_t)bc * T_ * HW_ + p;
    float prev = 0.f, cur = src[0];
#pragma unroll
    for (int t = 0; t < T_; t++) {
        float nxt = (t < T_ - 1) ? src[(size_t)(t + 1) * HW_] : 0.f;
        out[((size_t)((b * T_ + t) * C_ + c)) * HW_ + p] = k0 * prev + k1 * cur + k2 * nxt;
        prev = cur;
        cur = nxt;
    }
}

// ---------------- launch ----------------
extern "C" void kernel_launch(void* const* d_in, const int* in_sizes, int n_in,
                              void* d_out, int out_size) {
    const float* x      = (const float*)d_in[0];
    const float* w_sp   = (const float*)d_in[1];
    const float* w_red  = (const float*)d_in[2];
    const float* gam    = (const float*)d_in[3];
    const float* bet    = (const float*)d_in[4];
    const float* mea    = (const float*)d_in[5];
    const float* var    = (const float*)d_in[6];
    const float* w_exp  = (const float*)d_in[7];
    const float* wfc1   = (const float*)d_in[8];
    const float* bfc1   = (const float*)d_in[9];
    const float* wfc2   = (const float*)d_in[10];
    const float* bfc2   = (const float*)d_in[11];
    float* out = (float*)d_out;

    k_prep<<<192, 256>>>(w_red, w_exp);
    k_maxmean<<<dim3(13, B_ * T_), 256>>>(x);
    k_spatial<<<dim3(13, B_ * T_), 256>>>(w_sp);
    k_reduce<<<dim3(HW_ / PXT, B_), 128>>>(x, gam, bet, mea, var);
    k_expand<<<dim3(NPB, T_, B_), 256>>>(x);
    k_dyn<<<8, 256>>>(wfc1, bfc1, wfc2, bfc2);
    k_stencil<<<dim3(13, B_ * C_), 256>>>(out);
}

// round 8
// speedup vs baseline: 1.2491x; 1.0209x over previous
#include <cuda_runtime.h>
#include <math.h>
#include <stdint.h>

#define B_    8
#define T_    8
#define C_    256
#define CH_   64
#define Wd    56
#define HW_   3136
#define PT    128
#define NPB   25          // ceil(HW_/PT) for expand
#define PXT   16          // px per block in k_reduce (HW_/PXT = 196 exact)

typedef unsigned long long ull;

// ---------------- scratch (device globals) ----------------
__device__ float g_maxavg[(size_t)B_ * T_ * 2 * HW_];
__device__ float g_gate[(size_t)B_ * T_ * HW_];
__device__ __align__(16) float g_wrf[C_ * 3 * CH_];     // [c*192 + dt*64 + ch] plain f32
__device__ __align__(16) float g_we[CH_ * C_];          // [cin*256 + cout]
__device__ __align__(16) float g_t[(size_t)B_ * CH_ * T_ * HW_];
__device__ __align__(16) float g_xt[(size_t)B_ * C_ * T_ * HW_];
__device__ float g_vpart[(size_t)B_ * C_ * T_ * NPB];
__device__ float g_kern[B_ * C_ * 3];

// ---------------- helpers ----------------
__device__ __forceinline__ void ffma2(ull& d, ull a, ull b) {
    asm("fma.rn.f32x2 %0, %1, %2, %0;" : "+l"(d) : "l"(a), "l"(b));
}
__device__ __forceinline__ ull packdup(float w) {
    ull u; asm("mov.b64 %0, {%1, %1};" : "=l"(u) : "f"(w)); return u;
}
__device__ __forceinline__ float2 unpk(ull u) {
    float2 f; asm("mov.b64 {%0, %1}, %2;" : "=f"(f.x), "=f"(f.y) : "l"(u)); return f;
}
__device__ __forceinline__ unsigned sptr(const void* p) {
    return (unsigned)__cvta_generic_to_shared(p);
}
__device__ __forceinline__ void cpasync16(unsigned dst, const void* src) {
    asm volatile("cp.async.ca.shared.global [%0], [%1], 16;" :: "r"(dst), "l"(src));
}
__device__ __forceinline__ void cp_commit() { asm volatile("cp.async.commit_group;"); }
__device__ __forceinline__ void cp_wait0()  { asm volatile("cp.async.wait_group 0;"); }

// ---------------- prep: weight transposes ----------------
__global__ void k_prep(const float* __restrict__ wr, const float* __restrict__ we) {
    int idx = blockIdx.x * blockDim.x + threadIdx.x;
    if (idx < C_ * 3 * CH_) {
        int c = idx / 192;
        int r = idx % 192;
        int dt = r / 64, ch = r % 64;
        g_wrf[idx] = wr[ch * (C_ * 3) + c * 3 + dt];
    }
    if (idx < CH_ * C_) {
        int cout = idx & 255, cin = idx >> 8;
        g_we[idx] = we[cout * CH_ + cin];
    }
}

// ---------------- channel max/mean (float4) ----------------
__global__ __launch_bounds__(256) void k_maxmean(const float* __restrict__ x) {
    int bt = blockIdx.y;
    int p4 = blockIdx.x * blockDim.x + threadIdx.x;
    if (p4 >= HW_ / 4) return;
    const float4* xp = (const float4*)(x + (size_t)bt * C_ * HW_) + p4;
    float4 mx = xp[0];
    float4 sm = mx;
#pragma unroll 4
    for (int c = 1; c < C_; c++) {
        float4 v = xp[(size_t)c * (HW_ / 4)];
        mx.x = fmaxf(mx.x, v.x); mx.y = fmaxf(mx.y, v.y);
        mx.z = fmaxf(mx.z, v.z); mx.w = fmaxf(mx.w, v.w);
        sm.x += v.x; sm.y += v.y; sm.z += v.z; sm.w += v.w;
    }
    float4* mo = (float4*)(g_maxavg + (size_t)bt * 2 * HW_);
    mo[p4] = mx;
    sm.x *= (1.f / C_); sm.y *= (1.f / C_); sm.z *= (1.f / C_); sm.w *= (1.f / C_);
    mo[HW_ / 4 + p4] = sm;
}

// ---------------- 7x7 conv -> spatial gate ----------------
__global__ __launch_bounds__(256) void k_spatial(const float* __restrict__ w) {
    __shared__ float sw[98];
    int tid = threadIdx.x;
    if (tid < 98) sw[tid] = w[tid];
    __syncthreads();
    int bt = blockIdx.y;
    int p = blockIdx.x * blockDim.x + tid;
    if (p >= HW_) return;
    int py = p / Wd, px = p % Wd;
    const float* mb = g_maxavg + (size_t)bt * 2 * HW_;
    float s = 0.f;
#pragma unroll
    for (int ky = 0; ky < 7; ky++) {
        int iy = py + ky - 3;
        if (iy < 0 || iy >= Wd) continue;
#pragma unroll
        for (int kx = 0; kx < 7; kx++) {
            int ix = px + kx - 3;
            if (ix < 0 || ix >= Wd) continue;
            float m = mb[iy * Wd + ix];
            float a = mb[HW_ + iy * Wd + ix];
            s += sw[ky * 7 + kx] * m + sw[49 + ky * 7 + kx] * a;
        }
    }
    g_gate[(size_t)bt * HW_ + p] = 1.f + 1.f / (1.f + __expf(-s));
}

// ---------------- t-batched gated reduce conv3d + BN + relu ----------------
// Block: (px-tile of 16, b). ALL 8 output t's per block. Chunks of 16 c.
// 128 thr = 4 warps; lane = 16(chg) x 2(pxg); lane tile 4ch x 8t x 2px.
__global__ __launch_bounds__(128) void k_reduce(
    const float* __restrict__ x, const float* __restrict__ gamma,
    const float* __restrict__ beta, const float* __restrict__ mean,
    const float* __restrict__ var) {
    __shared__ float sinv[64], sbias[64];
    __shared__ __align__(16) ull sg[8][8];          // gate pairs [tin][pair]
    __shared__ __align__(16) ull sxs[16][8][10];    // [c][pair][slot] slot=tin+1, 10KB
    __shared__ __align__(16) float swf[2][3072];    // weights f32, 24KB dbl-buffered

    int tid = threadIdx.x;
    int warp = tid >> 5, lane = tid & 31;
    int chg = lane & 15, pxg = lane >> 4;
    int pair = warp * 2 + pxg;                      // 0..7
    int p0 = blockIdx.x * PXT;
    int b = blockIdx.y;

    if (tid < 64) {
        float iv = gamma[tid] * rsqrtf(var[tid] + 1e-5f);
        sinv[tid] = iv;
        sbias[tid] = beta[tid] - mean[tid] * iv;
        int tin = tid >> 3, pr = tid & 7;
        float2 g = *(const float2*)(g_gate + (size_t)(b * T_ + tin) * HW_ + p0 + pr * 2);
        sg[tin][pr] = *(ull*)&g;
    }
    // zero pads (slots 0 and 9), persist across chunks
    {
        int c = tid >> 3, pr = tid & 7;
        sxs[c][pr][0] = 0ULL;
        sxs[c][pr][9] = 0ULL;
    }
    __syncthreads();

    // staging decode: two c's per thread: sc and sc+8
    int sc = tid >> 4, sp = tid & 7, shalf = (tid >> 3) & 1;
    const float* xb = x + ((size_t)b * T_ * C_) * HW_ + p0 + sp * 2;
    float2 sgate[4];
#pragma unroll
    for (int k = 0; k < 4; k++) {
        ull g = sg[shalf * 4 + k][sp];
        sgate[k] = unpk(g);
    }

    unsigned swf_s = sptr(&swf[0][0]);

    // prologue: w chunk0 via cp.async (16c x 192 f32 = 12KB = 768 x 16B, 6/thread)
#pragma unroll
    for (int k = 0; k < 6; k++) {
        int q = tid + k * 128;
        cpasync16(swf_s + q * 16, g_wrf + q * 4);
    }
    cp_commit();
    // x chunk0 prefetch: 8 float2 (2 c-groups x 4 tin)
    float2 xf[8];
#pragma unroll
    for (int g = 0; g < 2; g++)
#pragma unroll
        for (int k = 0; k < 4; k++) {
            int tin = shalf * 4 + k;
            xf[g * 4 + k] = *(const float2*)(xb + ((size_t)(tin * C_ + sc + g * 8)) * HW_);
        }

    ull acc[4][8];
#pragma unroll
    for (int i = 0; i < 4; i++)
#pragma unroll
        for (int t = 0; t < 8; t++) acc[i][t] = 0ULL;

    for (int c0 = 0; c0 < C_; c0 += 16) {
        int buf = (c0 >> 4) & 1;
        __syncthreads();                 // xs free from previous compute
#pragma unroll
        for (int g = 0; g < 2; g++)
#pragma unroll
            for (int k = 0; k < 4; k++) {
                float2 v;
                v.x = xf[g * 4 + k].x * sgate[k].x;
                v.y = xf[g * 4 + k].y * sgate[k].y;
                sxs[sc + g * 8][sp][1 + shalf * 4 + k] = *(ull*)&v;
            }
        cp_wait0();
        __syncthreads();                 // xs + swf[buf] visible

        if (c0 + 16 < C_) {
#pragma unroll
            for (int k = 0; k < 6; k++) {
                int q = tid + k * 128;
                cpasync16(swf_s + (buf ^ 1) * 12288 + q * 16,
                          g_wrf + (c0 + 16) * 192 + q * 4);
            }
            cp_commit();
#pragma unroll
            for (int g = 0; g < 2; g++)
#pragma unroll
                for (int k = 0; k < 4; k++) {
                    int tin = shalf * 4 + k;
                    xf[g * 4 + k] = *(const float2*)(xb + ((size_t)(tin * C_ + c0 + 16 + sc + g * 8)) * HW_);
                }
        }

#pragma unroll 2
        for (int cc = 0; cc < 16; cc++) {
            const ulonglong2* xp2 = (const ulonglong2*)&sxs[cc][pair][0];
            ulonglong2 a0 = xp2[0], a1 = xp2[1], a2 = xp2[2], a3 = xp2[3], a4 = xp2[4];
            ull xv[10] = {a0.x, a0.y, a1.x, a1.y, a2.x, a2.y, a3.x, a3.y, a4.x, a4.y};
#pragma unroll
            for (int dt = 0; dt < 3; dt++) {
                float4 wq = *(const float4*)&swf[buf][cc * 192 + dt * 64 + chg * 4];
                ull w0 = packdup(wq.x), w1 = packdup(wq.y);
                ull w2 = packdup(wq.z), w3 = packdup(wq.w);
#pragma unroll
                for (int t = 0; t < 8; t++) {
                    ffma2(acc[0][t], w0, xv[t + dt]);
                    ffma2(acc[1][t], w1, xv[t + dt]);
                    ffma2(acc[2][t], w2, xv[t + dt]);
                    ffma2(acc[3][t], w3, xv[t + dt]);
                }
            }
        }
    }

    // epilogue: BN + relu, lane writes 4ch x 8t x 2px
    int px = p0 + pair * 2;
#pragma unroll
    for (int i = 0; i < 4; i++) {
        int ch = chg * 4 + i;
        float inv = sinv[ch], bia = sbias[ch];
        float* dst = g_t + (((size_t)(b * CH_ + ch)) * T_) * HW_ + px;
#pragma unroll
        for (int t = 0; t < 8; t++) {
            float2 f = unpk(acc[i][t]);
            float2 o;
            o.x = fmaxf(fmaf(f.x, inv, bia), 0.f);
            o.y = fmaxf(fmaf(f.y, inv, bia), 0.f);
            *(float2*)(dst + (size_t)t * HW_) = o;
        }
    }
}

// ---------------- expand 1x1x1 GEMM (256 x 128, K=64) + sigmoid + x_t + v partials ----------------
// 128 thr = 4 warps x 32 px; lane = 8(cog) x 4(pxg); lane tile 8co x 8px; 4 co-chunks.
__global__ __launch_bounds__(128) void k_expand(const float* __restrict__ x) {
    __shared__ __align__(16) float st[CH_][PT];         // 32KB
    __shared__ __align__(16) float swi[2][CH_ * 64];    // 32KB dbl-buffered
    __shared__ float sred[4][64];                       // 1KB

    int tid = threadIdx.x;
    int p0 = blockIdx.x * PT;
    int t = blockIdx.y, b = blockIdx.z;
    int warp = tid >> 5, lane = tid & 31;
    int cog = lane & 7, pxg = lane >> 3;
    int pxb = warp * 32 + pxg * 8;
    bool pv = (p0 + pxb < HW_);

    unsigned st_s = sptr(&st[0][0]);
    unsigned swi_s = sptr(&swi[0][0]);

    // prologue: stage t-tile (32KB) + weight chunk0 (16KB) via cp.async
    const float* tsrc = g_t + ((size_t)(b * CH_ * T_ + t)) * HW_;
#pragma unroll
    for (int k = 0; k < 16; k++) {
        int q = tid + k * 128;            // < 2048 16B units
        int cin = q >> 5, c16 = q & 31;
        if (p0 + c16 * 4 < HW_)
            cpasync16(st_s + q * 16, tsrc + (size_t)cin * T_ * HW_ + p0 + c16 * 4);
        else
            *(float4*)&st[cin][c16 * 4] = make_float4(0.f, 0.f, 0.f, 0.f);
    }
#pragma unroll
    for (int k = 0; k < 8; k++) {
        int q = tid + k * 128;            // < 1024
        int cin = q >> 4, q16 = q & 15;
        cpasync16(swi_s + q * 16, g_we + cin * 256 + q16 * 4);
    }
    cp_commit();

    float4 gvA = make_float4(0.f, 0.f, 0.f, 0.f), gvB = gvA;
    if (pv) {
        const float* gp = g_gate + (size_t)(b * T_ + t) * HW_ + p0 + pxb;
        gvA = *(const float4*)gp;
        gvB = *(const float4*)(gp + 4);
    }

    for (int chunk = 0; chunk < 4; chunk++) {
        int buf = chunk & 1;
        cp_wait0();
        __syncthreads();

        if (chunk < 3) {
#pragma unroll
            for (int k = 0; k < 8; k++) {
                int q = tid + k * 128;
                int cin = q >> 4, q16 = q & 15;
                cpasync16(swi_s + (buf ^ 1) * 16384 + q * 16,
                          g_we + cin * 256 + (chunk + 1) * 64 + q16 * 4);
            }
            cp_commit();
        }

        ull acc[8][4];
#pragma unroll
        for (int i = 0; i < 8; i++)
#pragma unroll
            for (int j = 0; j < 4; j++) acc[i][j] = 0ULL;

#pragma unroll 4
        for (int cin = 0; cin < CH_; cin++) {
            float4 wlo = *(const float4*)&swi[buf][cin * 64 + cog * 8];
            float4 whi = *(const float4*)&swi[buf][cin * 64 + cog * 8 + 4];
            ull wd[8];
            wd[0] = packdup(wlo.x); wd[1] = packdup(wlo.y);
            wd[2] = packdup(wlo.z); wd[3] = packdup(wlo.w);
            wd[4] = packdup(whi.x); wd[5] = packdup(whi.y);
            wd[6] = packdup(whi.z); wd[7] = packdup(whi.w);
            ulonglong2 xa = *(const ulonglong2*)(const void*)&st[cin][pxb];
            ulonglong2 xc = *(const ulonglong2*)(const void*)&st[cin][pxb + 4];
            ull xv[4] = {xa.x, xa.y, xc.x, xc.y};
#pragma unroll
            for (int i = 0; i < 8; i++)
#pragma unroll
                for (int j = 0; j < 4; j++)
                    ffma2(acc[i][j], wd[i], xv[j]);
        }

        // epilogue: x_t = x*gate*(1+sigmoid)  [1+sig(s) = 2 - 1/(1+e^s)]
        float psum[8];
#pragma unroll
        for (int i = 0; i < 8; i++) {
            psum[i] = 0.f;
            if (pv) {
                int co = chunk * 64 + cog * 8 + i;
                const float* xsrc = x + ((size_t)((b * T_ + t) * C_ + co)) * HW_ + p0 + pxb;
                float* dst = g_xt + ((size_t)((b * C_ + co) * T_ + t)) * HW_ + p0 + pxb;
                float4 xA = *(const float4*)xsrc, xB = *(const float4*)(xsrc + 4);
                float2 f0 = unpk(acc[i][0]), f1 = unpk(acc[i][1]);
                float2 f2 = unpk(acc[i][2]), f3 = unpk(acc[i][3]);
                float4 oA, oB;
                oA.x = xA.x * gvA.x * (2.f - 1.f / (1.f + __expf(f0.x)));
                oA.y = xA.y * gvA.y * (2.f - 1.f / (1.f + __expf(f0.y)));
                oA.z = xA.z * gvA.z * (2.f - 1.f / (1.f + __expf(f1.x)));
                oA.w = xA.w * gvA.w * (2.f - 1.f / (1.f + __expf(f1.y)));
                oB.x = xB.x * gvB.x * (2.f - 1.f / (1.f + __expf(f2.x)));
                oB.y = xB.y * gvB.y * (2.f - 1.f / (1.f + __expf(f2.y)));
                oB.z = xB.z * gvB.z * (2.f - 1.f / (1.f + __expf(f3.x)));
                oB.w = xB.w * gvB.w * (2.f - 1.f / (1.f + __expf(f3.y)));
                *(float4*)dst = oA;
                *(float4*)(dst + 4) = oB;
                psum[i] = (oA.x + oA.y) + (oA.z + oA.w) + (oB.x + oB.y) + (oB.z + oB.w);
            }
        }
#pragma unroll
        for (int i = 0; i < 8; i++) {
            psum[i] += __shfl_xor_sync(0xffffffffu, psum[i], 8);
            psum[i] += __shfl_xor_sync(0xffffffffu, psum[i], 16);
        }
        if (pxg == 0) {
#pragma unroll
            for (int i = 0; i < 8; i++) sred[warp][cog * 8 + i] = psum[i];
        }
        __syncthreads();
        if (tid < 64) {
            float s = sred[0][tid] + sred[1][tid] + sred[2][tid] + sred[3][tid];
            g_vpart[((size_t)((b * C_ + chunk * 64 + tid) * T_ + t)) * NPB + blockIdx.x] = s;
        }
    }
}

// ---------------- dynamic temporal kernel ----------------
__global__ __launch_bounds__(256) void k_dyn(
    const float* __restrict__ wfc1, const float* __restrict__ bfc1,
    const float* __restrict__ wfc2, const float* __restrict__ bfc2) {
    int id = blockIdx.x * blockDim.x + threadIdx.x;
    if (id >= B_ * C_) return;
    float v[T_];
#pragma unroll
    for (int t = 0; t < T_; t++) {
        const float* pp = g_vpart + ((size_t)id * T_ + t) * NPB;
        float s = 0.f;
#pragma unroll
        for (int k = 0; k < NPB; k++) s += pp[k];
        v[t] = s * (1.f / HW_);
    }
    float lg[3] = {bfc2[0], bfc2[1], bfc2[2]};
#pragma unroll
    for (int hh = 0; hh < 16; hh++) {
        float s = bfc1[hh];
#pragma unroll
        for (int t = 0; t < T_; t++) s += wfc1[hh * 8 + t] * v[t];
        s = fmaxf(s, 0.f);
#pragma unroll
        for (int k = 0; k < 3; k++) lg[k] += wfc2[k * 16 + hh] * s;
    }
    float m = fmaxf(lg[0], fmaxf(lg[1], lg[2]));
    float e0 = __expf(lg[0] - m), e1 = __expf(lg[1] - m), e2 = __expf(lg[2] - m);
    float inv = 1.f / (e0 + e1 + e2);
    g_kern[id * 3 + 0] = e0 * inv;
    g_kern[id * 3 + 1] = e1 * inv;
    g_kern[id * 3 + 2] = e2 * inv;
}

// ---------------- depthwise temporal stencil (float4) ----------------
__global__ __launch_bounds__(256) void k_stencil(float* __restrict__ out) {
    int p4 = blockIdx.x * blockDim.x + threadIdx.x;
    if (p4 >= HW_ / 4) return;
    int bc = blockIdx.y;
    int b = bc >> 8, c = bc & 255;
    float k0 = g_kern[bc * 3 + 0];
    float k1 = g_kern[bc * 3 + 1];
    float k2 = g_kern[bc * 3 + 2];
    const float4* src = (const float4*)(g_xt + (size_t)bc * T_ * HW_) + p4;
    float4* dst = (float4*)out;
    float4 prev = make_float4(0.f, 0.f, 0.f, 0.f);
    float4 cur = src[0];
#pragma unroll
    for (int t = 0; t < T_; t++) {
        float4 nxt = (t < T_ - 1) ? src[(size_t)(t + 1) * (HW_ / 4)]
                                  : make_float4(0.f, 0.f, 0.f, 0.f);
        float4 o;
        o.x = k0 * prev.x + k1 * cur.x + k2 * nxt.x;
        o.y = k0 * prev.y + k1 * cur.y + k2 * nxt.y;
        o.z = k0 * prev.z + k1 * cur.z + k2 * nxt.z;
        o.w = k0 * prev.w + k1 * cur.w + k2 * nxt.w;
        dst[((size_t)((b * T_ + t) * C_ + c)) * (HW_ / 4) + p4] = o;
        prev = cur;
        cur = nxt;
    }
}

// ---------------- launch ----------------
extern "C" void kernel_launch(void* const* d_in, const int* in_sizes, int n_in,
                              void* d_out, int out_size) {
    const float* x      = (const float*)d_in[0];
    const float* w_sp   = (const float*)d_in[1];
    const float* w_red  = (const float*)d_in[2];
    const float* gam    = (const float*)d_in[3];
    const float* bet    = (const float*)d_in[4];
    const float* mea    = (const float*)d_in[5];
    const float* var    = (const float*)d_in[6];
    const float* w_exp  = (const float*)d_in[7];
    const float* wfc1   = (const float*)d_in[8];
    const float* bfc1   = (const float*)d_in[9];
    const float* wfc2   = (const float*)d_in[10];
    const float* bfc2   = (const float*)d_in[11];
    float* out = (float*)d_out;

    k_prep<<<192, 256>>>(w_red, w_exp);
    k_maxmean<<<dim3(4, B_ * T_), 256>>>(x);
    k_spatial<<<dim3(13, B_ * T_), 256>>>(w_sp);
    k_reduce<<<dim3(HW_ / PXT, B_), 128>>>(x, gam, bet, mea, var);
    k_expand<<<dim3(NPB, T_, B_), 128>>>(x);
    k_dyn<<<8, 256>>>(wfc1, bfc1, wfc2, bfc2);
    k_stencil<<<dim3(4, B_ * C_), 256>>>(out);
}

// round 9
// speedup vs baseline: 1.2811x; 1.0256x over previous
#include <cuda_runtime.h>
#include <cuda_fp16.h>
#include <math.h>
#include <stdint.h>

#define B_    8
#define T_    8
#define C_    256
#define CH_   64
#define Wd    56
#define HW_   3136
#define PT    128
#define NPB   25          // ceil(HW_/PT) for expand
#define PXT   16          // px per block in k_reduce

typedef unsigned long long ull;

// ---------------- scratch (device globals) ----------------
__device__ float g_maxavg[(size_t)B_ * T_ * 2 * HW_];
__device__ float g_gate[(size_t)B_ * T_ * HW_];
__device__ __align__(16) float g_wrf[C_ * 3 * CH_];     // [c*192 + dt*64 + ch]
__device__ __align__(16) float g_we[CH_ * C_];          // [cin*256 + cout]
__device__ __align__(16) float g_t[(size_t)B_ * CH_ * T_ * HW_];
__device__ __align__(16) __half2 g_xth[(size_t)B_ * C_ * T_ * HW_ / 2];  // fp16 x_t
__device__ float g_vpart[(size_t)B_ * C_ * T_ * NPB];
__device__ float g_kern[B_ * C_ * 3];

// ---------------- helpers ----------------
__device__ __forceinline__ void ffma2(ull& d, ull a, ull b) {
    asm("fma.rn.f32x2 %0, %1, %2, %0;" : "+l"(d) : "l"(a), "l"(b));
}
__device__ __forceinline__ ull packdup(float w) {
    ull u; asm("mov.b64 %0, {%1, %1};" : "=l"(u) : "f"(w)); return u;
}
__device__ __forceinline__ float2 unpk(ull u) {
    float2 f; asm("mov.b64 {%0, %1}, %2;" : "=f"(f.x), "=f"(f.y) : "l"(u)); return f;
}
__device__ __forceinline__ unsigned sptr(const void* p) {
    return (unsigned)__cvta_generic_to_shared(p);
}
__device__ __forceinline__ void cpasync16(unsigned dst, const void* src) {
    asm volatile("cp.async.ca.shared.global [%0], [%1], 16;" :: "r"(dst), "l"(src));
}
__device__ __forceinline__ void cp_commit() { asm volatile("cp.async.commit_group;"); }
__device__ __forceinline__ void cp_wait0()  { asm volatile("cp.async.wait_group 0;"); }

// ---------------- prep: weight transposes ----------------
__global__ void k_prep(const float* __restrict__ wr, const float* __restrict__ we) {
    int idx = blockIdx.x * blockDim.x + threadIdx.x;
    if (idx < C_ * 3 * CH_) {
        int c = idx / 192;
        int r = idx % 192;
        int dt = r / 64, ch = r % 64;
        g_wrf[idx] = wr[ch * (C_ * 3) + c * 3 + dt];
    }
    if (idx < CH_ * C_) {
        int cout = idx & 255, cin = idx >> 8;
        g_we[idx] = we[cout * CH_ + cin];
    }
}

// ---------------- channel max/mean (float4) ----------------
__global__ __launch_bounds__(256) void k_maxmean(const float* __restrict__ x) {
    int bt = blockIdx.y;
    int p4 = blockIdx.x * blockDim.x + threadIdx.x;
    if (p4 >= HW_ / 4) return;
    const float4* xp = (const float4*)(x + (size_t)bt * C_ * HW_) + p4;
    float4 mx = xp[0];
    float4 sm = mx;
#pragma unroll 4
    for (int c = 1; c < C_; c++) {
        float4 v = xp[(size_t)c * (HW_ / 4)];
        mx.x = fmaxf(mx.x, v.x); mx.y = fmaxf(mx.y, v.y);
        mx.z = fmaxf(mx.z, v.z); mx.w = fmaxf(mx.w, v.w);
        sm.x += v.x; sm.y += v.y; sm.z += v.z; sm.w += v.w;
    }
    float4* mo = (float4*)(g_maxavg + (size_t)bt * 2 * HW_);
    mo[p4] = mx;
    sm.x *= (1.f / C_); sm.y *= (1.f / C_); sm.z *= (1.f / C_); sm.w *= (1.f / C_);
    mo[HW_ / 4 + p4] = sm;
}

// ---------------- 7x7 conv -> spatial gate ----------------
__global__ __launch_bounds__(256) void k_spatial(const float* __restrict__ w) {
    __shared__ float sw[98];
    int tid = threadIdx.x;
    if (tid < 98) sw[tid] = w[tid];
    __syncthreads();
    int bt = blockIdx.y;
    int p = blockIdx.x * blockDim.x + tid;
    if (p >= HW_) return;
    int py = p / Wd, px = p % Wd;
    const float* mb = g_maxavg + (size_t)bt * 2 * HW_;
    float s = 0.f;
#pragma unroll
    for (int ky = 0; ky < 7; ky++) {
        int iy = py + ky - 3;
        if (iy < 0 || iy >= Wd) continue;
#pragma unroll
        for (int kx = 0; kx < 7; kx++) {
            int ix = px + kx - 3;
            if (ix < 0 || ix >= Wd) continue;
            float m = mb[iy * Wd + ix];
            float a = mb[HW_ + iy * Wd + ix];
            s += sw[ky * 7 + kx] * m + sw[49 + ky * 7 + kx] * a;
        }
    }
    g_gate[(size_t)bt * HW_ + p] = 1.f + 1.f / (1.f + __expf(-s));
}

// ---------------- t-batched gated reduce conv3d + BN + relu (R7 proven config) ----------------
__global__ __launch_bounds__(128) void k_reduce(
    const float* __restrict__ x, const float* __restrict__ gamma,
    const float* __restrict__ beta, const float* __restrict__ mean,
    const float* __restrict__ var) {
    __shared__ float sinv[64], sbias[64];
    __shared__ __align__(16) ull sg[8][8];
    __shared__ __align__(16) ull sxs[8][8][10];
    __shared__ __align__(16) float swf[2][1536];

    int tid = threadIdx.x;
    int warp = tid >> 5, lane = tid & 31;
    int chg = lane & 15, pxg = lane >> 4;
    int pair = warp * 2 + pxg;
    int p0 = blockIdx.x * PXT;
    int b = blockIdx.y;

    if (tid < 64) {
        float iv = gamma[tid] * rsqrtf(var[tid] + 1e-5f);
        sinv[tid] = iv;
        sbias[tid] = beta[tid] - mean[tid] * iv;
        int tin = tid >> 3, pr = tid & 7;
        float2 g = *(const float2*)(g_gate + (size_t)(b * T_ + tin) * HW_ + p0 + pr * 2);
        sg[tin][pr] = *(ull*)&g;
    }
    {
        int c = tid >> 3, pr = tid & 7;
        if (c < 8) {
            sxs[c][pr][0] = 0ULL;
            sxs[c][pr][9] = 0ULL;
        }
    }
    __syncthreads();

    int sc = tid >> 4, sp = tid & 7, shalf = (tid >> 3) & 1;
    const float* xb = x + ((size_t)b * T_ * C_) * HW_ + p0 + sp * 2;
    float2 sgate[4];
#pragma unroll
    for (int k = 0; k < 4; k++) {
        ull g = sg[shalf * 4 + k][sp];
        sgate[k] = unpk(g);
    }

    unsigned swf_s = sptr(&swf[0][0]);

#pragma unroll
    for (int k = 0; k < 3; k++) {
        int q = tid + k * 128;
        cpasync16(swf_s + q * 16, g_wrf + q * 4);
    }
    cp_commit();
    float2 xf[4];
#pragma unroll
    for (int k = 0; k < 4; k++) {
        int tin = shalf * 4 + k;
        xf[k] = *(const float2*)(xb + ((size_t)(tin * C_ + sc)) * HW_);
    }

    ull acc[4][8];
#pragma unroll
    for (int i = 0; i < 4; i++)
#pragma unroll
        for (int t = 0; t < 8; t++) acc[i][t] = 0ULL;

    for (int c0 = 0; c0 < C_; c0 += 8) {
        int buf = (c0 >> 3) & 1;
        __syncthreads();
#pragma unroll
        for (int k = 0; k < 4; k++) {
            float2 v;
            v.x = xf[k].x * sgate[k].x;
            v.y = xf[k].y * sgate[k].y;
            sxs[sc][sp][1 + shalf * 4 + k] = *(ull*)&v;
        }
        cp_wait0();
        __syncthreads();

        if (c0 + 8 < C_) {
#pragma unroll
            for (int k = 0; k < 3; k++) {
                int q = tid + k * 128;
                cpasync16(swf_s + (buf ^ 1) * 6144 + q * 16,
                          g_wrf + (c0 + 8) * 192 + q * 4);
            }
            cp_commit();
#pragma unroll
            for (int k = 0; k < 4; k++) {
                int tin = shalf * 4 + k;
                xf[k] = *(const float2*)(xb + ((size_t)(tin * C_ + c0 + 8 + sc)) * HW_);
            }
        }

#pragma unroll 2
        for (int cc = 0; cc < 8; cc++) {
            const ulonglong2* xp2 = (const ulonglong2*)&sxs[cc][pair][0];
            ulonglong2 a0 = xp2[0], a1 = xp2[1], a2 = xp2[2], a3 = xp2[3], a4 = xp2[4];
            ull xv[10] = {a0.x, a0.y, a1.x, a1.y, a2.x, a2.y, a3.x, a3.y, a4.x, a4.y};
#pragma unroll
            for (int dt = 0; dt < 3; dt++) {
                float4 wq = *(const float4*)&swf[buf][cc * 192 + dt * 64 + chg * 4];
                ull w0 = packdup(wq.x), w1 = packdup(wq.y);
                ull w2 = packdup(wq.z), w3 = packdup(wq.w);
#pragma unroll
                for (int t = 0; t < 8; t++) {
                    ffma2(acc[0][t], w0, xv[t + dt]);
                    ffma2(acc[1][t], w1, xv[t + dt]);
                    ffma2(acc[2][t], w2, xv[t + dt]);
                    ffma2(acc[3][t], w3, xv[t + dt]);
                }
            }
        }
    }

    int px = p0 + pair * 2;
#pragma unroll
    for (int i = 0; i < 4; i++) {
        int ch = chg * 4 + i;
        float inv = sinv[ch], bia = sbias[ch];
        float* dst = g_t + (((size_t)(b * CH_ + ch)) * T_) * HW_ + px;
#pragma unroll
        for (int t = 0; t < 8; t++) {
            float2 f = unpk(acc[i][t]);
            float2 o;
            o.x = fmaxf(fmaf(f.x, inv, bia), 0.f);
            o.y = fmaxf(fmaf(f.y, inv, bia), 0.f);
            *(float2*)(dst + (size_t)t * HW_) = o;
        }
    }
}

// ---------------- expand 1x1x1 GEMM (256 x 128, K=64) + sigmoid + x_t(fp16) + v partials ----------------
__global__ __launch_bounds__(128) void k_expand(const float* __restrict__ x) {
    __shared__ __align__(16) float st[CH_][PT];         // 32KB
    __shared__ __align__(16) float swi[2][CH_ * 64];    // 32KB dbl-buffered
    __shared__ float sred[4][64];                       // 1KB

    int tid = threadIdx.x;
    int p0 = blockIdx.x * PT;
    int t = blockIdx.y, b = blockIdx.z;
    int warp = tid >> 5, lane = tid & 31;
    int cog = lane & 7, pxg = lane >> 3;
    int pxb = warp * 32 + pxg * 8;
    bool pv = (p0 + pxb < HW_);

    unsigned st_s = sptr(&st[0][0]);
    unsigned swi_s = sptr(&swi[0][0]);

    const float* tsrc = g_t + ((size_t)(b * CH_ * T_ + t)) * HW_;
#pragma unroll
    for (int k = 0; k < 16; k++) {
        int q = tid + k * 128;
        int cin = q >> 5, c16 = q & 31;
        if (p0 + c16 * 4 < HW_)
            cpasync16(st_s + q * 16, tsrc + (size_t)cin * T_ * HW_ + p0 + c16 * 4);
        else
            *(float4*)&st[cin][c16 * 4] = make_float4(0.f, 0.f, 0.f, 0.f);
    }
#pragma unroll
    for (int k = 0; k < 8; k++) {
        int q = tid + k * 128;
        int cin = q >> 4, q16 = q & 15;
        cpasync16(swi_s + q * 16, g_we + cin * 256 + q16 * 4);
    }
    cp_commit();

    float4 gvA = make_float4(0.f, 0.f, 0.f, 0.f), gvB = gvA;
    if (pv) {
        const float* gp = g_gate + (size_t)(b * T_ + t) * HW_ + p0 + pxb;
        gvA = *(const float4*)gp;
        gvB = *(const float4*)(gp + 4);
    }

    for (int chunk = 0; chunk < 4; chunk++) {
        int buf = chunk & 1;
        cp_wait0();
        __syncthreads();

        if (chunk < 3) {
#pragma unroll
            for (int k = 0; k < 8; k++) {
                int q = tid + k * 128;
                int cin = q >> 4, q16 = q & 15;
                cpasync16(swi_s + (buf ^ 1) * 16384 + q * 16,
                          g_we + cin * 256 + (chunk + 1) * 64 + q16 * 4);
            }
            cp_commit();
        }

        ull acc[8][4];
#pragma unroll
        for (int i = 0; i < 8; i++)
#pragma unroll
            for (int j = 0; j < 4; j++) acc[i][j] = 0ULL;

#pragma unroll 4
        for (int cin = 0; cin < CH_; cin++) {
            float4 wlo = *(const float4*)&swi[buf][cin * 64 + cog * 8];
            float4 whi = *(const float4*)&swi[buf][cin * 64 + cog * 8 + 4];
            ull wd[8];
            wd[0] = packdup(wlo.x); wd[1] = packdup(wlo.y);
            wd[2] = packdup(wlo.z); wd[3] = packdup(wlo.w);
            wd[4] = packdup(whi.x); wd[5] = packdup(whi.y);
            wd[6] = packdup(whi.z); wd[7] = packdup(whi.w);
            ulonglong2 xa = *(const ulonglong2*)(const void*)&st[cin][pxb];
            ulonglong2 xc = *(const ulonglong2*)(const void*)&st[cin][pxb + 4];
            ull xv[4] = {xa.x, xa.y, xc.x, xc.y};
#pragma unroll
            for (int i = 0; i < 8; i++)
#pragma unroll
                for (int j = 0; j < 4; j++)
                    ffma2(acc[i][j], wd[i], xv[j]);
        }

        // epilogue: x_t = x*gate*(1+sigmoid) -> fp16 store; psum in fp32
        float psum[8];
#pragma unroll
        for (int i = 0; i < 8; i++) {
            psum[i] = 0.f;
            if (pv) {
                int co = chunk * 64 + cog * 8 + i;
                const float* xsrc = x + ((size_t)((b * T_ + t) * C_ + co)) * HW_ + p0 + pxb;
                float4 xA = *(const float4*)xsrc, xB = *(const float4*)(xsrc + 4);
                float2 f0 = unpk(acc[i][0]), f1 = unpk(acc[i][1]);
                float2 f2 = unpk(acc[i][2]), f3 = unpk(acc[i][3]);
                float4 oA, oB;
                oA.x = xA.x * gvA.x * (2.f - 1.f / (1.f + __expf(f0.x)));
                oA.y = xA.y * gvA.y * (2.f - 1.f / (1.f + __expf(f0.y)));
                oA.z = xA.z * gvA.z * (2.f - 1.f / (1.f + __expf(f1.x)));
                oA.w = xA.w * gvA.w * (2.f - 1.f / (1.f + __expf(f1.y)));
                oB.x = xB.x * gvB.x * (2.f - 1.f / (1.f + __expf(f2.x)));
                oB.y = xB.y * gvB.y * (2.f - 1.f / (1.f + __expf(f2.y)));
                oB.z = xB.z * gvB.z * (2.f - 1.f / (1.f + __expf(f3.x)));
                oB.w = xB.w * gvB.w * (2.f - 1.f / (1.f + __expf(f3.y)));
                __half2 h[4];
                h[0] = __floats2half2_rn(oA.x, oA.y);
                h[1] = __floats2half2_rn(oA.z, oA.w);
                h[2] = __floats2half2_rn(oB.x, oB.y);
                h[3] = __floats2half2_rn(oB.z, oB.w);
                *(uint4*)(g_xth + (((size_t)((b * C_ + co) * T_ + t)) * HW_ + p0 + pxb) / 2) =
                    *(const uint4*)h;
                psum[i] = (oA.x + oA.y) + (oA.z + oA.w) + (oB.x + oB.y) + (oB.z + oB.w);
            }
        }
#pragma unroll
        for (int i = 0; i < 8; i++) {
            psum[i] += __shfl_xor_sync(0xffffffffu, psum[i], 8);
            psum[i] += __shfl_xor_sync(0xffffffffu, psum[i], 16);
        }
        if (pxg == 0) {
#pragma unroll
            for (int i = 0; i < 8; i++) sred[warp][cog * 8 + i] = psum[i];
        }
        __syncthreads();
        if (tid < 64) {
            float s = sred[0][tid] + sred[1][tid] + sred[2][tid] + sred[3][tid];
            g_vpart[((size_t)((b * C_ + chunk * 64 + tid) * T_ + t)) * NPB + blockIdx.x] = s;
        }
    }
}

// ---------------- dynamic temporal kernel ----------------
__global__ __launch_bounds__(256) void k_dyn(
    const float* __restrict__ wfc1, const float* __restrict__ bfc1,
    const float* __restrict__ wfc2, const float* __restrict__ bfc2) {
    int id = blockIdx.x * blockDim.x + threadIdx.x;
    if (id >= B_ * C_) return;
    float v[T_];
#pragma unroll
    for (int t = 0; t < T_; t++) {
        const float* pp = g_vpart + ((size_t)id * T_ + t) * NPB;
        float s = 0.f;
#pragma unroll
        for (int k = 0; k < NPB; k++) s += pp[k];
        v[t] = s * (1.f / HW_);
    }
    float lg[3] = {bfc2[0], bfc2[1], bfc2[2]};
#pragma unroll
    for (int hh = 0; hh < 16; hh++) {
        float s = bfc1[hh];
#pragma unroll
        for (int t = 0; t < T_; t++) s += wfc1[hh * 8 + t] * v[t];
        s = fmaxf(s, 0.f);
#pragma unroll
        for (int k = 0; k < 3; k++) lg[k] += wfc2[k * 16 + hh] * s;
    }
    float m = fmaxf(lg[0], fmaxf(lg[1], lg[2]));
    float e0 = __expf(lg[0] - m), e1 = __expf(lg[1] - m), e2 = __expf(lg[2] - m);
    float inv = 1.f / (e0 + e1 + e2);
    g_kern[id * 3 + 0] = e0 * inv;
    g_kern[id * 3 + 1] = e1 * inv;
    g_kern[id * 3 + 2] = e2 * inv;
}

// ---------------- depthwise temporal stencil (fp16 in, fp32 out, 8px/thread) ----------------
__device__ __forceinline__ void cvt8(float* f, uint4 v) {
    __half2 h;
    *(unsigned*)&h = v.x; float2 a = __half22float2(h); f[0] = a.x; f[1] = a.y;
    *(unsigned*)&h = v.y; a = __half22float2(h); f[2] = a.x; f[3] = a.y;
    *(unsigned*)&h = v.z; a = __half22float2(h); f[4] = a.x; f[5] = a.y;
    *(unsigned*)&h = v.w; a = __half22float2(h); f[6] = a.x; f[7] = a.y;
}

__global__ __launch_bounds__(256) void k_stencil(float* __restrict__ out) {
    int p8 = blockIdx.x * blockDim.x + threadIdx.x;
    if (p8 >= HW_ / 8) return;       // 392
    int bc = blockIdx.y;
    int b = bc >> 8, c = bc & 255;
    float k0 = g_kern[bc * 3 + 0];
    float k1 = g_kern[bc * 3 + 1];
    float k2 = g_kern[bc * 3 + 2];
    const uint4* src = (const uint4*)(g_xth + (size_t)bc * T_ * (HW_ / 2)) + p8;
    float prev[8], cur[8], nxt[8];
#pragma unroll
    for (int i = 0; i < 8; i++) prev[i] = 0.f;
    cvt8(cur, src[0]);
#pragma unroll
    for (int t = 0; t < T_; t++) {
        if (t < T_ - 1) cvt8(nxt, src[(size_t)(t + 1) * (HW_ / 8)]);
        else {
#pragma unroll
            for (int i = 0; i < 8; i++) nxt[i] = 0.f;
        }
        float* dp = out + ((size_t)((b * T_ + t) * C_ + c)) * HW_ + p8 * 8;
        float4 o1, o2;
        o1.x = k0 * prev[0] + k1 * cur[0] + k2 * nxt[0];
        o1.y = k0 * prev[1] + k1 * cur[1] + k2 * nxt[1];
        o1.z = k0 * prev[2] + k1 * cur[2] + k2 * nxt[2];
        o1.w = k0 * prev[3] + k1 * cur[3] + k2 * nxt[3];
        o2.x = k0 * prev[4] + k1 * cur[4] + k2 * nxt[4];
        o2.y = k0 * prev[5] + k1 * cur[5] + k2 * nxt[5];
        o2.z = k0 * prev[6] + k1 * cur[6] + k2 * nxt[6];
        o2.w = k0 * prev[7] + k1 * cur[7] + k2 * nxt[7];
        *(float4*)dp = o1;
        *(float4*)(dp + 4) = o2;
#pragma unroll
        for (int i = 0; i < 8; i++) { prev[i] = cur[i]; cur[i] = nxt[i]; }
    }
}

// ---------------- launch ----------------
extern "C" void kernel_launch(void* const* d_in, const int* in_sizes, int n_in,
                              void* d_out, int out_size) {
    const float* x      = (const float*)d_in[0];
    const float* w_sp   = (const float*)d_in[1];
    const float* w_red  = (const float*)d_in[2];
    const float* gam    = (const float*)d_in[3];
    const float* bet    = (const float*)d_in[4];
    const float* mea    = (const float*)d_in[5];
    const float* var    = (const float*)d_in[6];
    const float* w_exp  = (const float*)d_in[7];
    const float* wfc1   = (const float*)d_in[8];
    const float* bfc1   = (const float*)d_in[9];
    const float* wfc2   = (const float*)d_in[10];
    const float* bfc2   = (const float*)d_in[11];
    float* out = (float*)d_out;

    k_prep<<<192, 256>>>(w_red, w_exp);
    k_maxmean<<<dim3(4, B_ * T_), 256>>>(x);
    k_spatial<<<dim3(13, B_ * T_), 256>>>(w_sp);
    k_reduce<<<dim3(HW_ / PXT, B_), 128>>>(x, gam, bet, mea, var);
    k_expand<<<dim3(NPB, T_, B_), 128>>>(x);
    k_dyn<<<8, 256>>>(wfc1, bfc1, wfc2, bfc2);
    k_stencil<<<dim3(2, B_ * C_), 256>>>(out);
}